// round 15
// baseline (speedup 1.0000x reference)
#include <cuda_runtime.h>
#include <cuda_bf16.h>
#include <cstdint>

#define Bsz 4
#define Cch 256
#define Nsp 4096
#define Gg  32
#define CPG 8

// ---------------- scratch (static device memory; no allocations) ------------
__device__ __nv_bfloat16 g_s[Bsz * Cch * Nsp];   // [b][c][i]
__device__ __nv_bfloat16 g_q[Bsz * Nsp * Cch];   // [b][i][c] (scaled by C^-1/2)
__device__ __nv_bfloat16 g_k[Bsz * Nsp * Cch];   // [b][j][c]
__device__ __nv_bfloat16 g_v[Bsz * Cch * Nsp];   // [b][c][j]
__device__ __nv_bfloat16 g_h[Bsz * Nsp * Cch];   // [b][i][c]
__device__ __nv_bfloat16 g_wq[Cch * Cch];        // bf16 weights
__device__ __nv_bfloat16 g_wk[Cch * Cch];
__device__ __nv_bfloat16 g_wv[Cch * Cch];
__device__ __nv_bfloat16 g_wp[Cch * Cch];

// ---------------- helpers -----------------------------------------------------
__device__ __forceinline__ uint32_t smem_u32(const void* p) {
    uint32_t a;
    asm("{ .reg .u64 t; cvta.to.shared.u64 t, %1; cvt.u32.u64 %0, t; }" : "=r"(a) : "l"(p));
    return a;
}
__device__ __forceinline__ void mma2(float* d, const uint32_t* a, uint32_t b0, uint32_t b1) {
    asm volatile(
        "mma.sync.aligned.m16n8k16.row.col.f32.bf16.bf16.f32 "
        "{%0,%1,%2,%3}, {%4,%5,%6,%7}, {%8,%9}, {%0,%1,%2,%3};\n"
        : "+f"(d[0]), "+f"(d[1]), "+f"(d[2]), "+f"(d[3])
        : "r"(a[0]), "r"(a[1]), "r"(a[2]), "r"(a[3]), "r"(b0), "r"(b1));
}
__device__ __forceinline__ void ldsm4(uint32_t* r, uint32_t addr) {
    asm volatile("ldmatrix.sync.aligned.m8n8.x4.shared.b16 {%0,%1,%2,%3}, [%4];"
                 : "=r"(r[0]), "=r"(r[1]), "=r"(r[2]), "=r"(r[3]) : "r"(addr));
}
__device__ __forceinline__ void ldsm4t(uint32_t* r, uint32_t addr) {
    asm volatile("ldmatrix.sync.aligned.m8n8.x4.trans.shared.b16 {%0,%1,%2,%3}, [%4];"
                 : "=r"(r[0]), "=r"(r[1]), "=r"(r[2]), "=r"(r[3]) : "r"(addr));
}
__device__ __forceinline__ void cp16(uint32_t saddr, const void* gaddr) {
    asm volatile("cp.async.cg.shared.global [%0], [%1], 16;" :: "r"(saddr), "l"(gaddr));
}
#define CP_COMMIT asm volatile("cp.async.commit_group;")
#define CP_WAIT(n) asm volatile("cp.async.wait_group %0;" :: "n"(n))
__device__ __forceinline__ float ex2(float a) {
    float d;
    asm("ex2.approx.ftz.f32 %0, %1;" : "=f"(d) : "f"(a));
    return d;
}

// ---------------- weight fp32 -> bf16 conversion -----------------------------
__global__ __launch_bounds__(256) void wcvt_kernel(const float* __restrict__ wq,
                                                   const float* __restrict__ wk,
                                                   const float* __restrict__ wv,
                                                   const float* __restrict__ wp) {
    int m = blockIdx.y;
    const float* src = (m == 0) ? wq : (m == 1) ? wk : (m == 2) ? wv : wp;
    __nv_bfloat16* dst = (m == 0) ? g_wq : (m == 1) ? g_wk : (m == 2) ? g_wv : g_wp;
    int idx = blockIdx.x * 256 + threadIdx.x;
    float4 v = ((const float4*)src)[idx];
    __nv_bfloat162 h0 = __floats2bfloat162_rn(v.x, v.y);
    __nv_bfloat162 h1 = __floats2bfloat162_rn(v.z, v.w);
    uint2 u;
    u.x = *reinterpret_cast<uint32_t*>(&h0);
    u.y = *reinterpret_cast<uint32_t*>(&h1);
    ((uint2*)dst)[idx] = u;
}

// ---------------- GroupNorm --> bf16 s ---------------------------------------
__global__ __launch_bounds__(256) void gn_kernel(const float* __restrict__ x,
                                                 const float* __restrict__ gamma,
                                                 const float* __restrict__ beta) {
    int bg = blockIdx.x;
    int b = bg >> 5;
    int g = bg & 31;
    const float4* xp = (const float4*)(x + ((size_t)b * Cch + g * CPG) * Nsp);
    const int total4 = CPG * Nsp / 4;

    float sum = 0.f, sq = 0.f;
    for (int i = threadIdx.x; i < total4; i += 256) {
        float4 v = xp[i];
        sum += v.x + v.y + v.z + v.w;
        sq  += v.x * v.x + v.y * v.y + v.z * v.z + v.w * v.w;
    }
    for (int off = 16; off > 0; off >>= 1) {
        sum += __shfl_xor_sync(0xffffffffu, sum, off);
        sq  += __shfl_xor_sync(0xffffffffu, sq, off);
    }
    __shared__ float ws[8], wq2[8];
    int warp = threadIdx.x >> 5, lane = threadIdx.x & 31;
    if (lane == 0) { ws[warp] = sum; wq2[warp] = sq; }
    __syncthreads();
    if (threadIdx.x == 0) {
        float s = 0.f, q = 0.f;
        for (int i = 0; i < 8; i++) { s += ws[i]; q += wq2[i]; }
        ws[0] = s; wq2[0] = q;
    }
    __syncthreads();
    const float invn = 1.0f / (float)(CPG * Nsp);
    float mean = ws[0] * invn;
    float var  = wq2[0] * invn - mean * mean;
    float rstd = rsqrtf(var + 1e-6f);

    __nv_bfloat162* sp = (__nv_bfloat162*)(g_s + ((size_t)b * Cch + g * CPG) * Nsp);
    for (int i = threadIdx.x; i < total4; i += 256) {
        float4 v = xp[i];
        int c = g * CPG + (i >> 10);
        float a  = rstd * gamma[c];
        float bb = beta[c] - mean * a;
        sp[2 * i]     = __floats2bfloat162_rn(v.x * a + bb, v.y * a + bb);
        sp[2 * i + 1] = __floats2bfloat162_rn(v.z * a + bb, v.w * a + bb);
    }
}

// ---------------- QKV 1x1 conv (single-pass, trans via ldmatrix) --------------
#define WSTR 264
#define SSTR 136
#define QK_WS 0
#define QK_SS (256 * WSTR * 2)                  // 135168
#define QKV_SMEM (QK_SS + 256 * SSTR * 2)       // 204800

__global__ __launch_bounds__(256, 1) void qkv_kernel(const float* __restrict__ bq,
                                                     const float* __restrict__ bk,
                                                     const float* __restrict__ bv) {
    extern __shared__ __align__(128) char smem[];
    const uint32_t sb = smem_u32(smem);
    int z = blockIdx.z;
    int b = z & 3;
    int w = z >> 2;
    const __nv_bfloat16* W = (w == 0) ? g_wq : (w == 1) ? g_wk : g_wv;
    const float* bia = (w == 0) ? bq : (w == 1) ? bk : bv;
    float scale = (w == 0) ? 0.0625f : 1.0f;
    const int i0 = blockIdx.x * 128;

    const int tid = threadIdx.x, lane = tid & 31, warp = tid >> 5;
    const int g = lane >> 2, qt = lane & 3;
    const int lr = lane & 15, lk = (lane >> 4) * 8;
    const int tr = (lane & 7) + ((lane >> 4) & 1) * 8;
    const int tc = ((lane >> 3) & 1) * 8;

#pragma unroll
    for (int kk = 0; kk < 32; kk++) {
        int idx = tid + kk * 256;
        int o = idx >> 5, c8 = (idx & 31) * 8;
        cp16(sb + QK_WS + (o * WSTR + c8) * 2, W + (size_t)o * Cch + c8);
    }
#pragma unroll
    for (int kk = 0; kk < 16; kk++) {
        int idx = tid + kk * 256;
        int c = idx >> 4, i8 = (idx & 15) * 8;
        cp16(sb + QK_SS + (c * SSTR + i8) * 2,
             g_s + ((size_t)b * Cch + c) * Nsp + i0 + i8);
    }
    CP_COMMIT;
    CP_WAIT(0);
    __syncthreads();

    float acc[2][16][4];
#pragma unroll
    for (int mm = 0; mm < 2; mm++)
#pragma unroll
        for (int nn = 0; nn < 16; nn++)
#pragma unroll
            for (int r = 0; r < 4; r++) acc[mm][nn][r] = 0.f;

    if (w < 2) {
        const int mbase = (warp & 3) * 32, nbase = (warp >> 2) * 128;
#pragma unroll
        for (int ks = 0; ks < 16; ks++) {
            uint32_t a0[4], a1[4];
            ldsm4t(a0, sb + QK_SS + ((ks * 16 + tr) * SSTR + mbase + tc) * 2);
            ldsm4t(a1, sb + QK_SS + ((ks * 16 + tr) * SSTR + mbase + 16 + tc) * 2);
#pragma unroll
            for (int ng = 0; ng < 8; ng++) {
                uint32_t bb[4];
                ldsm4(bb, sb + QK_WS + ((nbase + ng * 16 + lr) * WSTR + ks * 16 + lk) * 2);
                mma2(acc[0][2 * ng],     a0, bb[0], bb[2]);
                mma2(acc[0][2 * ng + 1], a0, bb[1], bb[3]);
                mma2(acc[1][2 * ng],     a1, bb[0], bb[2]);
                mma2(acc[1][2 * ng + 1], a1, bb[1], bb[3]);
            }
        }
        __nv_bfloat16* op = ((w == 0) ? g_q : g_k) + (size_t)b * Nsp * Cch;
#pragma unroll
        for (int mm = 0; mm < 2; mm++) {
            int i_row = i0 + mbase + mm * 16 + g;
#pragma unroll
            for (int nn = 0; nn < 16; nn++) {
                int oc = nbase + nn * 8 + 2 * qt;
                float bia0 = bia[oc], bia1 = bia[oc + 1];
                __nv_bfloat162 p0 = __floats2bfloat162_rn((acc[mm][nn][0] + bia0) * scale,
                                                          (acc[mm][nn][1] + bia1) * scale);
                __nv_bfloat162 p1 = __floats2bfloat162_rn((acc[mm][nn][2] + bia0) * scale,
                                                          (acc[mm][nn][3] + bia1) * scale);
                *(__nv_bfloat162*)(op + (size_t)i_row * Cch + oc) = p0;
                *(__nv_bfloat162*)(op + (size_t)(i_row + 8) * Cch + oc) = p1;
            }
        }
    } else {
        const int mbase = warp * 32;
#pragma unroll
        for (int ks = 0; ks < 16; ks++) {
            uint32_t a0[4], a1[4];
            ldsm4(a0, sb + QK_WS + ((mbase + lr) * WSTR + ks * 16 + lk) * 2);
            ldsm4(a1, sb + QK_WS + ((mbase + 16 + lr) * WSTR + ks * 16 + lk) * 2);
#pragma unroll
            for (int ng = 0; ng < 8; ng++) {
                uint32_t bb[4];
                ldsm4t(bb, sb + QK_SS + ((ks * 16 + tr) * SSTR + ng * 16 + tc) * 2);
                mma2(acc[0][2 * ng],     a0, bb[0], bb[2]);
                mma2(acc[0][2 * ng + 1], a0, bb[1], bb[3]);
                mma2(acc[1][2 * ng],     a1, bb[0], bb[2]);
                mma2(acc[1][2 * ng + 1], a1, bb[1], bb[3]);
            }
        }
        __nv_bfloat16* op = g_v + (size_t)b * Cch * Nsp;
#pragma unroll
        for (int mm = 0; mm < 2; mm++) {
            int o_row = mbase + mm * 16 + g;
            float b0v = bia[o_row];
            float b1v = bia[o_row + 8];
#pragma unroll
            for (int nn = 0; nn < 16; nn++) {
                int col = i0 + nn * 8 + 2 * qt;
                __nv_bfloat162 p0 = __floats2bfloat162_rn(acc[mm][nn][0] + b0v,
                                                          acc[mm][nn][1] + b0v);
                __nv_bfloat162 p1 = __floats2bfloat162_rn(acc[mm][nn][2] + b1v,
                                                          acc[mm][nn][3] + b1v);
                *(__nv_bfloat162*)(op + (size_t)o_row * Nsp + col) = p0;
                *(__nv_bfloat162*)(op + (size_t)(o_row + 8) * Nsp + col) = p1;
            }
        }
    }
}

// ---------------- Fused flash attention (small CTA, 2 CTAs/SM) ---------------
// 128 threads (4 warps), 64 Q rows per CTA, 32-j tiles, 128 tiles.
// Q in registers (staged through the K smem region). 2 K + 2 V buffers.
// 74.8 KB smem/CTA -> 2 CTAs/SM -> 4 warps/SMSP from independent CTAs.
#define QSTR 264
#define VSTR 40           // V row stride (bf16): 80B = 5 x 16B, conflict-free
#define AKO  0
#define AKBUF (32 * QSTR * 2)                 // 16896
#define AVO  (2 * AKBUF)                      // 33792
#define AVBUF (256 * VSTR * 2)                // 20480
#define ATTN_SMEM (AVO + 2 * AVBUF)           // 74752

__global__ __launch_bounds__(128, 2) void attn_kernel() {
    extern __shared__ __align__(128) char smem[];
    const uint32_t sb = smem_u32(smem);
    const int tid = threadIdx.x, lane = tid & 31, warp = tid >> 5;
    const int g = lane >> 2, qt = lane & 3;
    const int R = warp * 16;        // warp's 16 query rows (of 64)
    const int b = blockIdx.y, i0 = blockIdx.x * 64;

    const __nv_bfloat16* qg = g_q + ((size_t)b * Nsp + i0) * Cch;
    const __nv_bfloat16* kg = g_k + (size_t)b * Nsp * Cch;
    const __nv_bfloat16* vg = g_v + (size_t)b * Cch * Nsp;

    const int lr = lane & 15, lk = (lane >> 4) * 8;

    // ---- stage Q (64 rows) through the K region; load into registers ----
    uint32_t qf[16][4];
#pragma unroll
    for (int kk = 0; kk < 16; kk++) {
        int idx = tid + kk * 128;
        int row = idx >> 5, c = (idx & 31) * 8;
        cp16(sb + AKO + (row * QSTR + c) * 2, qg + (size_t)row * Cch + c);
    }
    CP_COMMIT;
    CP_WAIT(0);
    __syncthreads();
    {
        const uint32_t qfb = sb + AKO + ((R + lr) * QSTR + lk) * 2;
#pragma unroll
        for (int ks = 0; ks < 16; ks++) ldsm4(qf[ks], qfb + ks * 32);
    }
    __syncthreads();   // all reads done before K overwrites

    // ---- prologue: G0 = {K0,V0 -> buf0}; G1 = {K1,V1 -> buf1} ----
#pragma unroll
    for (int kk = 0; kk < 8; kk++) {
        int idx = tid + kk * 128;
        int row = idx >> 5, c = (idx & 31) * 8;
        cp16(sb + AKO + (row * QSTR + c) * 2, kg + (size_t)row * Cch + c);
    }
#pragma unroll
    for (int kk = 0; kk < 8; kk++) {
        int idx = tid + kk * 128;
        int row = idx >> 2, c = (idx & 3) * 8;
        cp16(sb + AVO + (row * VSTR + c) * 2, vg + (size_t)row * Nsp + c);
    }
    CP_COMMIT;
#pragma unroll
    for (int kk = 0; kk < 8; kk++) {
        int idx = tid + kk * 128;
        int row = idx >> 5, c = (idx & 31) * 8;
        cp16(sb + AKO + AKBUF + (row * QSTR + c) * 2, kg + (size_t)(32 + row) * Cch + c);
    }
#pragma unroll
    for (int kk = 0; kk < 8; kk++) {
        int idx = tid + kk * 128;
        int row = idx >> 2, c = (idx & 3) * 8;
        cp16(sb + AVO + AVBUF + (row * VSTR + c) * 2, vg + (size_t)row * Nsp + 32 + c);
    }
    CP_COMMIT;
    CP_WAIT(1);
    __syncthreads();

    float o_acc[32][4];
#pragma unroll
    for (int nt = 0; nt < 32; nt++)
#pragma unroll
        for (int r = 0; r < 4; r++) o_acc[nt][r] = 0.f;
    float l0 = 0.f, l1 = 0.f;
    const float LOG2E = 1.4426950408889634f;

    for (int t = 0; t < 128; t++) {
        const int buf = t & 1;
        const uint32_t kfb = sb + AKO + buf * AKBUF + (lr * QSTR + lk) * 2;
        const uint32_t vfb = sb + AVO + buf * AVBUF + (lr * VSTR + lk) * 2;

        // ---- S = Q K^T : 16 rows x 32 j ----
        float s_acc[4][4];
#pragma unroll
        for (int nt = 0; nt < 4; nt++)
#pragma unroll
            for (int r = 0; r < 4; r++) s_acc[nt][r] = 0.f;
#pragma unroll
        for (int ks = 0; ks < 16; ks++) {
#pragma unroll
            for (int jg = 0; jg < 2; jg++) {
                uint32_t kb_[4];
                ldsm4(kb_, kfb + jg * (16 * QSTR * 2) + ks * 32);
                mma2(s_acc[2 * jg],     qf[ks], kb_[0], kb_[2]);
                mma2(s_acc[2 * jg + 1], qf[ks], kb_[1], kb_[3]);
            }
        }

        // ---- P = exp(S); l; PV A-frags ----
        uint32_t pf[2][4];
#pragma unroll
        for (int kh = 0; kh < 2; kh++) {
#pragma unroll
            for (int hf2 = 0; hf2 < 2; hf2++) {
                int nt = 2 * kh + hf2;
                float p0 = ex2(s_acc[nt][0] * LOG2E);
                float p1 = ex2(s_acc[nt][1] * LOG2E);
                float p2 = ex2(s_acc[nt][2] * LOG2E);
                float p3 = ex2(s_acc[nt][3] * LOG2E);
                l0 += p0 + p1;
                l1 += p2 + p3;
                __nv_bfloat162 h0 = __floats2bfloat162_rn(p0, p1);
                __nv_bfloat162 h1 = __floats2bfloat162_rn(p2, p3);
                pf[kh][2 * hf2]     = *reinterpret_cast<uint32_t*>(&h0);
                pf[kh][2 * hf2 + 1] = *reinterpret_cast<uint32_t*>(&h1);
            }
        }

        // ---- O += P V^T : 16 rows x 256 ch, k = 32 j ----
#pragma unroll
        for (int kh = 0; kh < 2; kh++) {
#pragma unroll
            for (int ct = 0; ct < 16; ct++) {
                uint32_t vb_[4];
                ldsm4(vb_, vfb + ct * (16 * VSTR * 2) + kh * 32);
                mma2(o_acc[2 * ct],     pf[kh], vb_[0], vb_[2]);
                mma2(o_acc[2 * ct + 1], pf[kh], vb_[1], vb_[3]);
            }
        }

        CP_WAIT(0);        // tile t+1 arrived
        __syncthreads();   // visible; this buf reusable

        if (t < 126) {     // prefetch tile t+2 into this buf
            const int tt = t + 2;
#pragma unroll
            for (int kk = 0; kk < 8; kk++) {
                int idx = tid + kk * 128;
                int row = idx >> 5, c = (idx & 31) * 8;
                cp16(sb + AKO + buf * AKBUF + (row * QSTR + c) * 2,
                     kg + (size_t)(tt * 32 + row) * Cch + c);
            }
#pragma unroll
            for (int kk = 0; kk < 8; kk++) {
                int idx = tid + kk * 128;
                int row = idx >> 2, c = (idx & 3) * 8;
                cp16(sb + AVO + buf * AVBUF + (row * VSTR + c) * 2,
                     vg + (size_t)row * Nsp + tt * 32 + c);
            }
            CP_COMMIT;
        }
    }

    // ---- l: quad reduction only ----
    l0 += __shfl_xor_sync(0xffffffffu, l0, 1);
    l0 += __shfl_xor_sync(0xffffffffu, l0, 2);
    l1 += __shfl_xor_sync(0xffffffffu, l1, 1);
    l1 += __shfl_xor_sync(0xffffffffu, l1, 2);
    float inv0 = 1.f / l0, inv1 = 1.f / l1;

    // ---- epilogue: O / l -> g_h [b][i][c] ----
    __nv_bfloat16* h0row = g_h + ((size_t)b * Nsp + i0 + R + g) * Cch;
    __nv_bfloat16* h1row = g_h + ((size_t)b * Nsp + i0 + R + g + 8) * Cch;
#pragma unroll
    for (int nt = 0; nt < 32; nt++) {
        int col = nt * 8 + 2 * qt;
        __nv_bfloat162 a0 = __floats2bfloat162_rn(o_acc[nt][0] * inv0, o_acc[nt][1] * inv0);
        __nv_bfloat162 a1 = __floats2bfloat162_rn(o_acc[nt][2] * inv1, o_acc[nt][3] * inv1);
        *(uint32_t*)(h0row + col) = *reinterpret_cast<uint32_t*>(&a0);
        *(uint32_t*)(h1row + col) = *reinterpret_cast<uint32_t*>(&a1);
    }
}

// ---------------- Proj (single-pass) + residual (fp32 out) -------------------
#define PWS 0
#define PHS (128 * WSTR * 2)                   // 67584
#define PROJ_SMEM (PHS + 128 * WSTR * 2)       // 135168

__global__ __launch_bounds__(256, 1) void proj_kernel(const float* __restrict__ bp,
                                                      const float* __restrict__ xin,
                                                      float* __restrict__ out) {
    extern __shared__ __align__(128) char smem[];
    const uint32_t sb = smem_u32(smem);
    const int b = blockIdx.z;
    const int i0 = blockIdx.x * 128;
    const int o0 = blockIdx.y * 128;

    const int tid = threadIdx.x, lane = tid & 31, warp = tid >> 5;
    const int g = lane >> 2, qt = lane & 3;
    const int lr = lane & 15, lk = (lane >> 4) * 8;
    const int wm = warp & 3, wn = warp >> 2;

#pragma unroll
    for (int kk = 0; kk < 16; kk++) {
        int idx = tid + kk * 256;
        int o = idx >> 5, c8 = (idx & 31) * 8;
        cp16(sb + PWS + (o * WSTR + c8) * 2, g_wp + (size_t)(o0 + o) * Cch + c8);
    }
#pragma unroll
    for (int kk = 0; kk < 16; kk++) {
        int idx = tid + kk * 256;
        int i = idx >> 5, c8 = (idx & 31) * 8;
        cp16(sb + PHS + (i * WSTR + c8) * 2, g_h + ((size_t)b * Nsp + i0 + i) * Cch + c8);
    }
    CP_COMMIT;
    CP_WAIT(0);
    __syncthreads();

    float acc[2][8][4];
#pragma unroll
    for (int mm = 0; mm < 2; mm++)
#pragma unroll
        for (int nn = 0; nn < 8; nn++)
#pragma unroll
            for (int r = 0; r < 4; r++) acc[mm][nn][r] = 0.f;

#pragma unroll
    for (int ks = 0; ks < 16; ks++) {
        uint32_t a0[4], a1[4];
        ldsm4(a0, sb + PWS + ((wm * 32 + lr) * WSTR + ks * 16 + lk) * 2);
        ldsm4(a1, sb + PWS + ((wm * 32 + 16 + lr) * WSTR + ks * 16 + lk) * 2);
#pragma unroll
        for (int ng = 0; ng < 4; ng++) {
            uint32_t bb[4];
            ldsm4(bb, sb + PHS + ((wn * 64 + ng * 16 + lr) * WSTR + ks * 16 + lk) * 2);
            mma2(acc[0][2 * ng],     a0, bb[0], bb[2]);
            mma2(acc[0][2 * ng + 1], a0, bb[1], bb[3]);
            mma2(acc[1][2 * ng],     a1, bb[0], bb[2]);
            mma2(acc[1][2 * ng + 1], a1, bb[1], bb[3]);
        }
    }

    const float* xp = xin + (size_t)b * Cch * Nsp;
    float* op = out + (size_t)b * Cch * Nsp;
#pragma unroll
    for (int mm = 0; mm < 2; mm++) {
        int o_row = o0 + wm * 32 + mm * 16 + g;
        float b0v = bp[o_row];
        float b1v = bp[o_row + 8];
#pragma unroll
        for (int nn = 0; nn < 8; nn++) {
            int col = i0 + wn * 64 + nn * 8 + 2 * qt;
            size_t idx0 = (size_t)o_row * Nsp + col;
            size_t idx1 = (size_t)(o_row + 8) * Nsp + col;
            float2 x0 = *(const float2*)(xp + idx0);
            float2 x1 = *(const float2*)(xp + idx1);
            float2 r0 = make_float2(acc[mm][nn][0] + b0v + x0.x, acc[mm][nn][1] + b0v + x0.y);
            float2 r1 = make_float2(acc[mm][nn][2] + b1v + x1.x, acc[mm][nn][3] + b1v + x1.y);
            *(float2*)(op + idx0) = r0;
            *(float2*)(op + idx1) = r1;
        }
    }
}

// ---------------- launch -----------------------------------------------------
extern "C" void kernel_launch(void* const* d_in, const int* in_sizes, int n_in,
                              void* d_out, int out_size) {
    (void)in_sizes; (void)n_in; (void)out_size;
    const float* x     = (const float*)d_in[0];
    const float* gamma = (const float*)d_in[1];
    const float* beta  = (const float*)d_in[2];
    const float* wq    = (const float*)d_in[3];
    const float* bq    = (const float*)d_in[4];
    const float* wk    = (const float*)d_in[5];
    const float* bk    = (const float*)d_in[6];
    const float* wv    = (const float*)d_in[7];
    const float* bv    = (const float*)d_in[8];
    const float* wp    = (const float*)d_in[9];
    const float* bp    = (const float*)d_in[10];
    float* out = (float*)d_out;

    wcvt_kernel<<<dim3(64, 4), 256>>>(wq, wk, wv, wp);
    gn_kernel<<<Bsz * Gg, 256>>>(x, gamma, beta);
    cudaFuncSetAttribute(qkv_kernel, cudaFuncAttributeMaxDynamicSharedMemorySize, QKV_SMEM);
    qkv_kernel<<<dim3(Nsp / 128, 1, 12), 256, QKV_SMEM>>>(bq, bk, bv);
    cudaFuncSetAttribute(attn_kernel, cudaFuncAttributeMaxDynamicSharedMemorySize, ATTN_SMEM);
    attn_kernel<<<dim3(Nsp / 64, Bsz), 128, ATTN_SMEM>>>();
    cudaFuncSetAttribute(proj_kernel, cudaFuncAttributeMaxDynamicSharedMemorySize, PROJ_SMEM);
    proj_kernel<<<dim3(Nsp / 128, Cch / 128, Bsz), 256, PROJ_SMEM>>>(bp, x, out);
}

// round 16
// speedup vs baseline: 1.1666x; 1.1666x over previous
#include <cuda_runtime.h>
#include <cuda_bf16.h>
#include <cstdint>

#define Bsz 4
#define Cch 256
#define Nsp 4096
#define Gg  32
#define CPG 8

// ---------------- scratch (static device memory; no allocations) ------------
__device__ __nv_bfloat16 g_s[Bsz * Cch * Nsp];   // [b][c][i]
__device__ __nv_bfloat16 g_q[Bsz * Nsp * Cch];   // [b][i][c] (scaled by C^-1/2)
__device__ __nv_bfloat16 g_k[Bsz * Nsp * Cch];   // [b][j][c]
__device__ __nv_bfloat16 g_v[Bsz * Cch * Nsp];   // [b][c][j]
__device__ __nv_bfloat16 g_h[Bsz * Nsp * Cch];   // [b][i][c]
__device__ __nv_bfloat16 g_wq[Cch * Cch];        // bf16 weights
__device__ __nv_bfloat16 g_wk[Cch * Cch];
__device__ __nv_bfloat16 g_wv[Cch * Cch];
__device__ __nv_bfloat16 g_wp[Cch * Cch];
__device__ float g_gnstat[Bsz * Gg * 2];         // mean, rstd per (b,group)

// ---------------- helpers -----------------------------------------------------
__device__ __forceinline__ uint32_t smem_u32(const void* p) {
    uint32_t a;
    asm("{ .reg .u64 t; cvta.to.shared.u64 t, %1; cvt.u32.u64 %0, t; }" : "=r"(a) : "l"(p));
    return a;
}
__device__ __forceinline__ void mma2(float* d, const uint32_t* a, uint32_t b0, uint32_t b1) {
    asm volatile(
        "mma.sync.aligned.m16n8k16.row.col.f32.bf16.bf16.f32 "
        "{%0,%1,%2,%3}, {%4,%5,%6,%7}, {%8,%9}, {%0,%1,%2,%3};\n"
        : "+f"(d[0]), "+f"(d[1]), "+f"(d[2]), "+f"(d[3])
        : "r"(a[0]), "r"(a[1]), "r"(a[2]), "r"(a[3]), "r"(b0), "r"(b1));
}
__device__ __forceinline__ void ldsm4(uint32_t* r, uint32_t addr) {
    asm volatile("ldmatrix.sync.aligned.m8n8.x4.shared.b16 {%0,%1,%2,%3}, [%4];"
                 : "=r"(r[0]), "=r"(r[1]), "=r"(r[2]), "=r"(r[3]) : "r"(addr));
}
__device__ __forceinline__ void ldsm4t(uint32_t* r, uint32_t addr) {
    asm volatile("ldmatrix.sync.aligned.m8n8.x4.trans.shared.b16 {%0,%1,%2,%3}, [%4];"
                 : "=r"(r[0]), "=r"(r[1]), "=r"(r[2]), "=r"(r[3]) : "r"(addr));
}
__device__ __forceinline__ void cp16(uint32_t saddr, const void* gaddr) {
    asm volatile("cp.async.cg.shared.global [%0], [%1], 16;" :: "r"(saddr), "l"(gaddr));
}
#define CP_COMMIT asm volatile("cp.async.commit_group;")
#define CP_WAIT(n) asm volatile("cp.async.wait_group %0;" :: "n"(n))
__device__ __forceinline__ float ex2(float a) {
    float d;
    asm("ex2.approx.ftz.f32 %0, %1;" : "=f"(d) : "f"(a));
    return d;
}

// ---------------- weight fp32 -> bf16 conversion -----------------------------
__global__ __launch_bounds__(256) void wcvt_kernel(const float* __restrict__ wq,
                                                   const float* __restrict__ wk,
                                                   const float* __restrict__ wv,
                                                   const float* __restrict__ wp) {
    int m = blockIdx.y;
    const float* src = (m == 0) ? wq : (m == 1) ? wk : (m == 2) ? wv : wp;
    __nv_bfloat16* dst = (m == 0) ? g_wq : (m == 1) ? g_wk : (m == 2) ? g_wv : g_wp;
    int idx = blockIdx.x * 256 + threadIdx.x;
    float4 v = ((const float4*)src)[idx];
    __nv_bfloat162 h0 = __floats2bfloat162_rn(v.x, v.y);
    __nv_bfloat162 h1 = __floats2bfloat162_rn(v.z, v.w);
    uint2 u;
    u.x = *reinterpret_cast<uint32_t*>(&h0);
    u.y = *reinterpret_cast<uint32_t*>(&h1);
    ((uint2*)dst)[idx] = u;
}

// ---------------- GroupNorm stats (mean, rstd per (b,g)) ---------------------
__global__ __launch_bounds__(256) void gn_stats_kernel(const float* __restrict__ x) {
    int bg = blockIdx.x;
    int b = bg >> 5;
    int g = bg & 31;
    const float4* xp = (const float4*)(x + ((size_t)b * Cch + g * CPG) * Nsp);
    const int total4 = CPG * Nsp / 4;

    float sum = 0.f, sq = 0.f;
    for (int i = threadIdx.x; i < total4; i += 256) {
        float4 v = xp[i];
        sum += v.x + v.y + v.z + v.w;
        sq  += v.x * v.x + v.y * v.y + v.z * v.z + v.w * v.w;
    }
    for (int off = 16; off > 0; off >>= 1) {
        sum += __shfl_xor_sync(0xffffffffu, sum, off);
        sq  += __shfl_xor_sync(0xffffffffu, sq, off);
    }
    __shared__ float ws[8], wq2[8];
    int warp = threadIdx.x >> 5, lane = threadIdx.x & 31;
    if (lane == 0) { ws[warp] = sum; wq2[warp] = sq; }
    __syncthreads();
    if (threadIdx.x == 0) {
        float s = 0.f, q = 0.f;
        for (int i = 0; i < 8; i++) { s += ws[i]; q += wq2[i]; }
        const float invn = 1.0f / (float)(CPG * Nsp);
        float mean = s * invn;
        float var  = q * invn - mean * mean;
        g_gnstat[2 * bg]     = mean;
        g_gnstat[2 * bg + 1] = rsqrtf(var + 1e-6f);
    }
}

// ---------------- GroupNorm apply (streaming, high occupancy) ----------------
__global__ __launch_bounds__(256) void gn_apply_kernel(const float* __restrict__ x,
                                                       const float* __restrict__ gamma,
                                                       const float* __restrict__ beta) {
    int idx = blockIdx.x * 256 + threadIdx.x;     // 1M work items x 4 floats
    int per_b = Cch * Nsp / 4;                     // 262144
    int b = idx / per_b;
    int within = idx - b * per_b;
    int c = within >> 10;                          // /(Nsp/4)
    int bg = b * 32 + (c >> 3);
    float mean = g_gnstat[2 * bg];
    float rstd = g_gnstat[2 * bg + 1];
    float a  = rstd * gamma[c];
    float bb = beta[c] - mean * a;
    float4 v = ((const float4*)x)[idx];
    __nv_bfloat162 h0 = __floats2bfloat162_rn(v.x * a + bb, v.y * a + bb);
    __nv_bfloat162 h1 = __floats2bfloat162_rn(v.z * a + bb, v.w * a + bb);
    uint2 u;
    u.x = *reinterpret_cast<uint32_t*>(&h0);
    u.y = *reinterpret_cast<uint32_t*>(&h1);
    ((uint2*)g_s)[idx] = u;
}

// ---------------- QKV 1x1 conv (single-pass, trans via ldmatrix) --------------
#define WSTR 264
#define SSTR 136
#define QK_WS 0
#define QK_SS (256 * WSTR * 2)                  // 135168
#define QKV_SMEM (QK_SS + 256 * SSTR * 2)       // 204800

__global__ __launch_bounds__(256, 1) void qkv_kernel(const float* __restrict__ bq,
                                                     const float* __restrict__ bk,
                                                     const float* __restrict__ bv) {
    extern __shared__ __align__(128) char smem[];
    const uint32_t sb = smem_u32(smem);
    int z = blockIdx.z;
    int b = z & 3;
    int w = z >> 2;
    const __nv_bfloat16* W = (w == 0) ? g_wq : (w == 1) ? g_wk : g_wv;
    const float* bia = (w == 0) ? bq : (w == 1) ? bk : bv;
    float scale = (w == 0) ? 0.0625f : 1.0f;
    const int i0 = blockIdx.x * 128;

    const int tid = threadIdx.x, lane = tid & 31, warp = tid >> 5;
    const int g = lane >> 2, qt = lane & 3;
    const int lr = lane & 15, lk = (lane >> 4) * 8;
    const int tr = (lane & 7) + ((lane >> 4) & 1) * 8;
    const int tc = ((lane >> 3) & 1) * 8;

#pragma unroll
    for (int kk = 0; kk < 32; kk++) {
        int idx = tid + kk * 256;
        int o = idx >> 5, c8 = (idx & 31) * 8;
        cp16(sb + QK_WS + (o * WSTR + c8) * 2, W + (size_t)o * Cch + c8);
    }
#pragma unroll
    for (int kk = 0; kk < 16; kk++) {
        int idx = tid + kk * 256;
        int c = idx >> 4, i8 = (idx & 15) * 8;
        cp16(sb + QK_SS + (c * SSTR + i8) * 2,
             g_s + ((size_t)b * Cch + c) * Nsp + i0 + i8);
    }
    CP_COMMIT;
    CP_WAIT(0);
    __syncthreads();

    float acc[2][16][4];
#pragma unroll
    for (int mm = 0; mm < 2; mm++)
#pragma unroll
        for (int nn = 0; nn < 16; nn++)
#pragma unroll
            for (int r = 0; r < 4; r++) acc[mm][nn][r] = 0.f;

    if (w < 2) {
        const int mbase = (warp & 3) * 32, nbase = (warp >> 2) * 128;
#pragma unroll
        for (int ks = 0; ks < 16; ks++) {
            uint32_t a0[4], a1[4];
            ldsm4t(a0, sb + QK_SS + ((ks * 16 + tr) * SSTR + mbase + tc) * 2);
            ldsm4t(a1, sb + QK_SS + ((ks * 16 + tr) * SSTR + mbase + 16 + tc) * 2);
#pragma unroll
            for (int ng = 0; ng < 8; ng++) {
                uint32_t bb[4];
                ldsm4(bb, sb + QK_WS + ((nbase + ng * 16 + lr) * WSTR + ks * 16 + lk) * 2);
                mma2(acc[0][2 * ng],     a0, bb[0], bb[2]);
                mma2(acc[0][2 * ng + 1], a0, bb[1], bb[3]);
                mma2(acc[1][2 * ng],     a1, bb[0], bb[2]);
                mma2(acc[1][2 * ng + 1], a1, bb[1], bb[3]);
            }
        }
        __nv_bfloat16* op = ((w == 0) ? g_q : g_k) + (size_t)b * Nsp * Cch;
#pragma unroll
        for (int mm = 0; mm < 2; mm++) {
            int i_row = i0 + mbase + mm * 16 + g;
#pragma unroll
            for (int nn = 0; nn < 16; nn++) {
                int oc = nbase + nn * 8 + 2 * qt;
                float bia0 = bia[oc], bia1 = bia[oc + 1];
                __nv_bfloat162 p0 = __floats2bfloat162_rn((acc[mm][nn][0] + bia0) * scale,
                                                          (acc[mm][nn][1] + bia1) * scale);
                __nv_bfloat162 p1 = __floats2bfloat162_rn((acc[mm][nn][2] + bia0) * scale,
                                                          (acc[mm][nn][3] + bia1) * scale);
                *(__nv_bfloat162*)(op + (size_t)i_row * Cch + oc) = p0;
                *(__nv_bfloat162*)(op + (size_t)(i_row + 8) * Cch + oc) = p1;
            }
        }
    } else {
        const int mbase = warp * 32;
#pragma unroll
        for (int ks = 0; ks < 16; ks++) {
            uint32_t a0[4], a1[4];
            ldsm4(a0, sb + QK_WS + ((mbase + lr) * WSTR + ks * 16 + lk) * 2);
            ldsm4(a1, sb + QK_WS + ((mbase + 16 + lr) * WSTR + ks * 16 + lk) * 2);
#pragma unroll
            for (int ng = 0; ng < 8; ng++) {
                uint32_t bb[4];
                ldsm4t(bb, sb + QK_SS + ((ks * 16 + tr) * SSTR + ng * 16 + tc) * 2);
                mma2(acc[0][2 * ng],     a0, bb[0], bb[2]);
                mma2(acc[0][2 * ng + 1], a0, bb[1], bb[3]);
                mma2(acc[1][2 * ng],     a1, bb[0], bb[2]);
                mma2(acc[1][2 * ng + 1], a1, bb[1], bb[3]);
            }
        }
        __nv_bfloat16* op = g_v + (size_t)b * Cch * Nsp;
#pragma unroll
        for (int mm = 0; mm < 2; mm++) {
            int o_row = mbase + mm * 16 + g;
            float b0v = bia[o_row];
            float b1v = bia[o_row + 8];
#pragma unroll
            for (int nn = 0; nn < 16; nn++) {
                int col = i0 + nn * 8 + 2 * qt;
                __nv_bfloat162 p0 = __floats2bfloat162_rn(acc[mm][nn][0] + b0v,
                                                          acc[mm][nn][1] + b0v);
                __nv_bfloat162 p1 = __floats2bfloat162_rn(acc[mm][nn][2] + b1v,
                                                          acc[mm][nn][3] + b1v);
                *(__nv_bfloat162*)(op + (size_t)o_row * Nsp + col) = p0;
                *(__nv_bfloat162*)(op + (size_t)(o_row + 8) * Nsp + col) = p1;
            }
        }
    }
}

// ---------------- Fused flash attention (round-13 core, best known) ----------
#define QSTR 264
#define VSTR 72
#define SQO  0
#define SKO  (128 * QSTR * 2)                 // 67584
#define SKBUF (64 * QSTR * 2)                 // 33792
#define SVO  (SKO + 2 * SKBUF)                // 135168
#define SVBUF (256 * VSTR * 2)                // 36864
#define ATTN_SMEM (SVO + 2 * SVBUF)           // 208896

__global__ __launch_bounds__(256, 1) void attn_kernel() {
    extern __shared__ __align__(128) char smem[];
    const uint32_t sb = smem_u32(smem);
    const int tid = threadIdx.x, lane = tid & 31, warp = tid >> 5;
    const int g = lane >> 2, qt = lane & 3;
    const int R = warp * 16;
    const int b = blockIdx.y, i0 = blockIdx.x * 128;

    const __nv_bfloat16* qg = g_q + ((size_t)b * Nsp + i0) * Cch;
    const __nv_bfloat16* kg = g_k + (size_t)b * Nsp * Cch;
    const __nv_bfloat16* vg = g_v + (size_t)b * Cch * Nsp;

#pragma unroll
    for (int kk = 0; kk < 16; kk++) {
        int idx = tid + kk * 256;
        int row = idx >> 5, c = (idx & 31) * 8;
        cp16(sb + SQO + (row * QSTR + c) * 2, qg + (size_t)row * Cch + c);
    }
#pragma unroll
    for (int kk = 0; kk < 8; kk++) {
        int idx = tid + kk * 256;
        int row = idx >> 5, c = (idx & 31) * 8;
        cp16(sb + SKO + (row * QSTR + c) * 2, kg + (size_t)row * Cch + c);
    }
#pragma unroll
    for (int kk = 0; kk < 8; kk++) {
        int idx = tid + kk * 256;
        int row = idx >> 3, c = (idx & 7) * 8;
        cp16(sb + SVO + (row * VSTR + c) * 2, vg + (size_t)row * Nsp + c);
    }
    CP_COMMIT;
#pragma unroll
    for (int kk = 0; kk < 8; kk++) {
        int idx = tid + kk * 256;
        int row = idx >> 5, c = (idx & 31) * 8;
        cp16(sb + SKO + SKBUF + (row * QSTR + c) * 2, kg + (size_t)(64 + row) * Cch + c);
    }
#pragma unroll
    for (int kk = 0; kk < 8; kk++) {
        int idx = tid + kk * 256;
        int row = idx >> 3, c = (idx & 7) * 8;
        cp16(sb + SVO + SVBUF + (row * VSTR + c) * 2, vg + (size_t)row * Nsp + 64 + c);
    }
    CP_COMMIT;
    CP_WAIT(1);
    __syncthreads();

    const int lr = lane & 15, lk = (lane >> 4) * 8;

    uint32_t qf[16][4];
    {
        const uint32_t qfb = sb + SQO + ((R + lr) * QSTR + lk) * 2;
#pragma unroll
        for (int ks = 0; ks < 16; ks++) ldsm4(qf[ks], qfb + ks * 32);
    }

    float o_acc[32][4];
#pragma unroll
    for (int nt = 0; nt < 32; nt++)
#pragma unroll
        for (int r = 0; r < 4; r++) o_acc[nt][r] = 0.f;
    float l0 = 0.f, l1 = 0.f;
    const float LOG2E = 1.4426950408889634f;

    for (int t = 0; t < 64; t++) {
        const int buf = t & 1;
        const uint32_t kfb = sb + SKO + buf * SKBUF + (lr * QSTR + lk) * 2;
        const uint32_t vfb = sb + SVO + buf * SVBUF + (lr * VSTR + lk) * 2;

#pragma unroll
        for (int jh = 0; jh < 2; jh++) {
            float s_acc[4][4];
#pragma unroll
            for (int nt = 0; nt < 4; nt++)
#pragma unroll
                for (int r = 0; r < 4; r++) s_acc[nt][r] = 0.f;
#pragma unroll
            for (int ks = 0; ks < 16; ks++) {
#pragma unroll
                for (int jg = 0; jg < 2; jg++) {
                    uint32_t bb[4];
                    ldsm4(bb, kfb + (jh * 2 + jg) * (16 * QSTR * 2) + ks * 32);
                    mma2(s_acc[2 * jg],     qf[ks], bb[0], bb[2]);
                    mma2(s_acc[2 * jg + 1], qf[ks], bb[1], bb[3]);
                }
            }

            uint32_t pf[2][4];
#pragma unroll
            for (int kh = 0; kh < 2; kh++) {
#pragma unroll
                for (int hf2 = 0; hf2 < 2; hf2++) {
                    int nt = 2 * kh + hf2;
                    float p0 = ex2(s_acc[nt][0] * LOG2E);
                    float p1 = ex2(s_acc[nt][1] * LOG2E);
                    float p2 = ex2(s_acc[nt][2] * LOG2E);
                    float p3 = ex2(s_acc[nt][3] * LOG2E);
                    l0 += p0 + p1;
                    l1 += p2 + p3;
                    __nv_bfloat162 h0 = __floats2bfloat162_rn(p0, p1);
                    __nv_bfloat162 h1 = __floats2bfloat162_rn(p2, p3);
                    pf[kh][2 * hf2]     = *reinterpret_cast<uint32_t*>(&h0);
                    pf[kh][2 * hf2 + 1] = *reinterpret_cast<uint32_t*>(&h1);
                }
            }

#pragma unroll
            for (int kh = 0; kh < 2; kh++) {
#pragma unroll
                for (int ct = 0; ct < 16; ct++) {
                    uint32_t bb[4];
                    ldsm4(bb, vfb + ct * (16 * VSTR * 2) + (jh * 2 + kh) * 32);
                    mma2(o_acc[2 * ct],     pf[kh], bb[0], bb[2]);
                    mma2(o_acc[2 * ct + 1], pf[kh], bb[1], bb[3]);
                }
            }
        }

        CP_WAIT(0);
        __syncthreads();

        if (t < 62) {
            const int tt = t + 2;
#pragma unroll
            for (int kk = 0; kk < 8; kk++) {
                int idx = tid + kk * 256;
                int row = idx >> 5, c = (idx & 31) * 8;
                cp16(sb + SKO + buf * SKBUF + (row * QSTR + c) * 2,
                     kg + (size_t)(tt * 64 + row) * Cch + c);
            }
#pragma unroll
            for (int kk = 0; kk < 8; kk++) {
                int idx = tid + kk * 256;
                int row = idx >> 3, c = (idx & 7) * 8;
                cp16(sb + SVO + buf * SVBUF + (row * VSTR + c) * 2,
                     vg + (size_t)row * Nsp + tt * 64 + c);
            }
            CP_COMMIT;
        }
    }

    l0 += __shfl_xor_sync(0xffffffffu, l0, 1);
    l0 += __shfl_xor_sync(0xffffffffu, l0, 2);
    l1 += __shfl_xor_sync(0xffffffffu, l1, 1);
    l1 += __shfl_xor_sync(0xffffffffu, l1, 2);
    float inv0 = 1.f / l0, inv1 = 1.f / l1;

    __nv_bfloat16* h0row = g_h + ((size_t)b * Nsp + i0 + R + g) * Cch;
    __nv_bfloat16* h1row = g_h + ((size_t)b * Nsp + i0 + R + g + 8) * Cch;
#pragma unroll
    for (int nt = 0; nt < 32; nt++) {
        int col = nt * 8 + 2 * qt;
        __nv_bfloat162 a0 = __floats2bfloat162_rn(o_acc[nt][0] * inv0, o_acc[nt][1] * inv0);
        __nv_bfloat162 a1 = __floats2bfloat162_rn(o_acc[nt][2] * inv1, o_acc[nt][3] * inv1);
        *(uint32_t*)(h0row + col) = *reinterpret_cast<uint32_t*>(&a0);
        *(uint32_t*)(h1row + col) = *reinterpret_cast<uint32_t*>(&a1);
    }
}

// ---------------- Proj (single-pass) + residual (fp32 out) -------------------
#define PWS 0
#define PHS (128 * WSTR * 2)                   // 67584
#define PROJ_SMEM (PHS + 128 * WSTR * 2)       // 135168

__global__ __launch_bounds__(256, 1) void proj_kernel(const float* __restrict__ bp,
                                                      const float* __restrict__ xin,
                                                      float* __restrict__ out) {
    extern __shared__ __align__(128) char smem[];
    const uint32_t sb = smem_u32(smem);
    const int b = blockIdx.z;
    const int i0 = blockIdx.x * 128;
    const int o0 = blockIdx.y * 128;

    const int tid = threadIdx.x, lane = tid & 31, warp = tid >> 5;
    const int g = lane >> 2, qt = lane & 3;
    const int lr = lane & 15, lk = (lane >> 4) * 8;
    const int wm = warp & 3, wn = warp >> 2;

#pragma unroll
    for (int kk = 0; kk < 16; kk++) {
        int idx = tid + kk * 256;
        int o = idx >> 5, c8 = (idx & 31) * 8;
        cp16(sb + PWS + (o * WSTR + c8) * 2, g_wp + (size_t)(o0 + o) * Cch + c8);
    }
#pragma unroll
    for (int kk = 0; kk < 16; kk++) {
        int idx = tid + kk * 256;
        int i = idx >> 5, c8 = (idx & 31) * 8;
        cp16(sb + PHS + (i * WSTR + c8) * 2, g_h + ((size_t)b * Nsp + i0 + i) * Cch + c8);
    }
    CP_COMMIT;
    CP_WAIT(0);
    __syncthreads();

    float acc[2][8][4];
#pragma unroll
    for (int mm = 0; mm < 2; mm++)
#pragma unroll
        for (int nn = 0; nn < 8; nn++)
#pragma unroll
            for (int r = 0; r < 4; r++) acc[mm][nn][r] = 0.f;

#pragma unroll
    for (int ks = 0; ks < 16; ks++) {
        uint32_t a0[4], a1[4];
        ldsm4(a0, sb + PWS + ((wm * 32 + lr) * WSTR + ks * 16 + lk) * 2);
        ldsm4(a1, sb + PWS + ((wm * 32 + 16 + lr) * WSTR + ks * 16 + lk) * 2);
#pragma unroll
        for (int ng = 0; ng < 4; ng++) {
            uint32_t bb[4];
            ldsm4(bb, sb + PHS + ((wn * 64 + ng * 16 + lr) * WSTR + ks * 16 + lk) * 2);
            mma2(acc[0][2 * ng],     a0, bb[0], bb[2]);
            mma2(acc[0][2 * ng + 1], a0, bb[1], bb[3]);
            mma2(acc[1][2 * ng],     a1, bb[0], bb[2]);
            mma2(acc[1][2 * ng + 1], a1, bb[1], bb[3]);
        }
    }

    const float* xp = xin + (size_t)b * Cch * Nsp;
    float* op = out + (size_t)b * Cch * Nsp;
#pragma unroll
    for (int mm = 0; mm < 2; mm++) {
        int o_row = o0 + wm * 32 + mm * 16 + g;
        float b0v = bp[o_row];
        float b1v = bp[o_row + 8];
#pragma unroll
        for (int nn = 0; nn < 8; nn++) {
            int col = i0 + wn * 64 + nn * 8 + 2 * qt;
            size_t idx0 = (size_t)o_row * Nsp + col;
            size_t idx1 = (size_t)(o_row + 8) * Nsp + col;
            float2 x0 = *(const float2*)(xp + idx0);
            float2 x1 = *(const float2*)(xp + idx1);
            float2 r0 = make_float2(acc[mm][nn][0] + b0v + x0.x, acc[mm][nn][1] + b0v + x0.y);
            float2 r1 = make_float2(acc[mm][nn][2] + b1v + x1.x, acc[mm][nn][3] + b1v + x1.y);
            *(float2*)(op + idx0) = r0;
            *(float2*)(op + idx1) = r1;
        }
    }
}

// ---------------- launch -----------------------------------------------------
extern "C" void kernel_launch(void* const* d_in, const int* in_sizes, int n_in,
                              void* d_out, int out_size) {
    (void)in_sizes; (void)n_in; (void)out_size;
    const float* x     = (const float*)d_in[0];
    const float* gamma = (const float*)d_in[1];
    const float* beta  = (const float*)d_in[2];
    const float* wq    = (const float*)d_in[3];
    const float* bq    = (const float*)d_in[4];
    const float* wk    = (const float*)d_in[5];
    const float* bk    = (const float*)d_in[6];
    const float* wv    = (const float*)d_in[7];
    const float* bv    = (const float*)d_in[8];
    const float* wp    = (const float*)d_in[9];
    const float* bp    = (const float*)d_in[10];
    float* out = (float*)d_out;

    wcvt_kernel<<<dim3(64, 4), 256>>>(wq, wk, wv, wp);
    gn_stats_kernel<<<Bsz * Gg, 256>>>(x);
    gn_apply_kernel<<<Bsz * Cch * Nsp / 1024, 256>>>(x, gamma, beta);
    cudaFuncSetAttribute(qkv_kernel, cudaFuncAttributeMaxDynamicSharedMemorySize, QKV_SMEM);
    qkv_kernel<<<dim3(Nsp / 128, 1, 12), 256, QKV_SMEM>>>(bq, bk, bv);
    cudaFuncSetAttribute(attn_kernel, cudaFuncAttributeMaxDynamicSharedMemorySize, ATTN_SMEM);
    attn_kernel<<<dim3(Nsp / 128, Bsz), 256, ATTN_SMEM>>>();
    cudaFuncSetAttribute(proj_kernel, cudaFuncAttributeMaxDynamicSharedMemorySize, PROJ_SMEM);
    proj_kernel<<<dim3(Nsp / 128, Cch / 128, Bsz), 256, PROJ_SMEM>>>(bp, x, out);
}

// round 17
// speedup vs baseline: 1.1891x; 1.0192x over previous
#include <cuda_runtime.h>
#include <cuda_bf16.h>
#include <cstdint>

#define Bsz 4
#define Cch 256
#define Nsp 4096
#define Gg  32
#define CPG 8

// ---------------- scratch (static device memory; no allocations) ------------
__device__ __nv_bfloat16 g_s[Bsz * Cch * Nsp];   // [b][c][i]
__device__ __nv_bfloat16 g_q[Bsz * Nsp * Cch];   // [b][i][c] (scaled by C^-1/2)
__device__ __nv_bfloat16 g_k[Bsz * Nsp * Cch];   // [b][j][c]
__device__ __nv_bfloat16 g_v[Bsz * Cch * Nsp];   // [b][c][j]
__device__ __nv_bfloat16 g_h[Bsz * Nsp * Cch];   // [b][i][c]
__device__ __nv_bfloat16 g_wq[Cch * Cch];        // bf16 weights
__device__ __nv_bfloat16 g_wk[Cch * Cch];
__device__ __nv_bfloat16 g_wv[Cch * Cch];
__device__ __nv_bfloat16 g_wp[Cch * Cch];

// ---------------- helpers -----------------------------------------------------
__device__ __forceinline__ uint32_t smem_u32(const void* p) {
    uint32_t a;
    asm("{ .reg .u64 t; cvta.to.shared.u64 t, %1; cvt.u32.u64 %0, t; }" : "=r"(a) : "l"(p));
    return a;
}
__device__ __forceinline__ void mma2(float* d, const uint32_t* a, uint32_t b0, uint32_t b1) {
    asm volatile(
        "mma.sync.aligned.m16n8k16.row.col.f32.bf16.bf16.f32 "
        "{%0,%1,%2,%3}, {%4,%5,%6,%7}, {%8,%9}, {%0,%1,%2,%3};\n"
        : "+f"(d[0]), "+f"(d[1]), "+f"(d[2]), "+f"(d[3])
        : "r"(a[0]), "r"(a[1]), "r"(a[2]), "r"(a[3]), "r"(b0), "r"(b1));
}
__device__ __forceinline__ void ldsm4(uint32_t* r, uint32_t addr) {
    asm volatile("ldmatrix.sync.aligned.m8n8.x4.shared.b16 {%0,%1,%2,%3}, [%4];"
                 : "=r"(r[0]), "=r"(r[1]), "=r"(r[2]), "=r"(r[3]) : "r"(addr));
}
__device__ __forceinline__ void ldsm4t(uint32_t* r, uint32_t addr) {
    asm volatile("ldmatrix.sync.aligned.m8n8.x4.trans.shared.b16 {%0,%1,%2,%3}, [%4];"
                 : "=r"(r[0]), "=r"(r[1]), "=r"(r[2]), "=r"(r[3]) : "r"(addr));
}
__device__ __forceinline__ void cp16(uint32_t saddr, const void* gaddr) {
    asm volatile("cp.async.cg.shared.global [%0], [%1], 16;" :: "r"(saddr), "l"(gaddr));
}
#define CP_COMMIT asm volatile("cp.async.commit_group;")
#define CP_WAIT(n) asm volatile("cp.async.wait_group %0;" :: "n"(n))
__device__ __forceinline__ float ex2(float a) {
    float d;
    asm("ex2.approx.ftz.f32 %0, %1;" : "=f"(d) : "f"(a));
    return d;
}

// ---------------- weight fp32 -> bf16 conversion -----------------------------
__global__ __launch_bounds__(256) void wcvt_kernel(const float* __restrict__ wq,
                                                   const float* __restrict__ wk,
                                                   const float* __restrict__ wv,
                                                   const float* __restrict__ wp) {
    int m = blockIdx.y;
    const float* src = (m == 0) ? wq : (m == 1) ? wk : (m == 2) ? wv : wp;
    __nv_bfloat16* dst = (m == 0) ? g_wq : (m == 1) ? g_wk : (m == 2) ? g_wv : g_wp;
    int idx = blockIdx.x * 256 + threadIdx.x;
    float4 v = ((const float4*)src)[idx];
    __nv_bfloat162 h0 = __floats2bfloat162_rn(v.x, v.y);
    __nv_bfloat162 h1 = __floats2bfloat162_rn(v.z, v.w);
    uint2 u;
    u.x = *reinterpret_cast<uint32_t*>(&h0);
    u.y = *reinterpret_cast<uint32_t*>(&h1);
    ((uint2*)dst)[idx] = u;
}

// ---------------- GroupNorm --> bf16 s ---------------------------------------
__global__ __launch_bounds__(256) void gn_kernel(const float* __restrict__ x,
                                                 const float* __restrict__ gamma,
                                                 const float* __restrict__ beta) {
    int bg = blockIdx.x;
    int b = bg >> 5;
    int g = bg & 31;
    const float4* xp = (const float4*)(x + ((size_t)b * Cch + g * CPG) * Nsp);
    const int total4 = CPG * Nsp / 4;

    float sum = 0.f, sq = 0.f;
    for (int i = threadIdx.x; i < total4; i += 256) {
        float4 v = xp[i];
        sum += v.x + v.y + v.z + v.w;
        sq  += v.x * v.x + v.y * v.y + v.z * v.z + v.w * v.w;
    }
    for (int off = 16; off > 0; off >>= 1) {
        sum += __shfl_xor_sync(0xffffffffu, sum, off);
        sq  += __shfl_xor_sync(0xffffffffu, sq, off);
    }
    __shared__ float ws[8], wq2[8];
    int warp = threadIdx.x >> 5, lane = threadIdx.x & 31;
    if (lane == 0) { ws[warp] = sum; wq2[warp] = sq; }
    __syncthreads();
    if (threadIdx.x == 0) {
        float s = 0.f, q = 0.f;
        for (int i = 0; i < 8; i++) { s += ws[i]; q += wq2[i]; }
        ws[0] = s; wq2[0] = q;
    }
    __syncthreads();
    const float invn = 1.0f / (float)(CPG * Nsp);
    float mean = ws[0] * invn;
    float var  = wq2[0] * invn - mean * mean;
    float rstd = rsqrtf(var + 1e-6f);

    __nv_bfloat162* sp = (__nv_bfloat162*)(g_s + ((size_t)b * Cch + g * CPG) * Nsp);
    for (int i = threadIdx.x; i < total4; i += 256) {
        float4 v = xp[i];
        int c = g * CPG + (i >> 10);
        float a  = rstd * gamma[c];
        float bb = beta[c] - mean * a;
        sp[2 * i]     = __floats2bfloat162_rn(v.x * a + bb, v.y * a + bb);
        sp[2 * i + 1] = __floats2bfloat162_rn(v.z * a + bb, v.w * a + bb);
    }
}

// ---------------- QKV v2: one CTA per (i0,b), 6-phase W pipeline --------------
// smem: 2 x W-half buffers [128][264] (double-buffered) + Ss [256][136].
// Phases p=0..5: matrix m=p>>1 (q,k,v), o-half = p&1. Ss staged ONCE.
// Per phase: compute 128 i x 128 o on resident W half while next half streams.
#define WSTR 264
#define SSTR 136
#define WBUF (128 * WSTR * 2)                   // 67584
#define QK_SS (2 * WBUF)                        // 135168
#define QKV_SMEM (QK_SS + 256 * SSTR * 2)       // 204800

__global__ __launch_bounds__(256, 1) void qkv_kernel(const float* __restrict__ bq,
                                                     const float* __restrict__ bk,
                                                     const float* __restrict__ bv) {
    extern __shared__ __align__(128) char smem[];
    const uint32_t sb = smem_u32(smem);
    const int b = blockIdx.y;
    const int i0 = blockIdx.x * 128;

    const int tid = threadIdx.x, lane = tid & 31, warp = tid >> 5;
    const int g = lane >> 2, qt = lane & 3;
    const int lr = lane & 15, lk = (lane >> 4) * 8;
    const int tr = (lane & 7) + ((lane >> 4) & 1) * 8;
    const int tc = ((lane >> 3) & 1) * 8;

    const __nv_bfloat16* wsrc0[3] = {g_wq, g_wk, g_wv};

    // ---- prologue: G0 = {Ss, W(phase0)}, G1 = {W(phase1)} ----
#pragma unroll
    for (int kk = 0; kk < 16; kk++) {
        int idx = tid + kk * 256;
        int c = idx >> 4, i8 = (idx & 15) * 8;
        cp16(sb + QK_SS + (c * SSTR + i8) * 2,
             g_s + ((size_t)b * Cch + c) * Nsp + i0 + i8);
    }
#pragma unroll
    for (int kk = 0; kk < 16; kk++) {
        int idx = tid + kk * 256;
        int o = idx >> 5, c8 = (idx & 31) * 8;
        cp16(sb + (o * WSTR + c8) * 2, g_wq + (size_t)o * Cch + c8);
    }
    CP_COMMIT;
#pragma unroll
    for (int kk = 0; kk < 16; kk++) {
        int idx = tid + kk * 256;
        int o = idx >> 5, c8 = (idx & 31) * 8;
        cp16(sb + WBUF + (o * WSTR + c8) * 2, g_wq + (size_t)(128 + o) * Cch + c8);
    }
    CP_COMMIT;
    CP_WAIT(1);
    __syncthreads();

    for (int p = 0; p < 6; p++) {
        const int m = p >> 1, half = p & 1;
        const uint32_t wb = sb + (p & 1) * WBUF;
        const float* bia = (m == 0) ? bq : (m == 1) ? bk : bv;
        const float scale = (m == 0) ? 0.0625f : 1.0f;

        if (m < 2) {
            // ---- q,k: D[i][o]; warp: 32 i x 64 o (of this 128-o half) ----
            const int mbase = (warp & 3) * 32, nbase = (warp >> 2) * 64;
            float acc[2][8][4];
#pragma unroll
            for (int mm = 0; mm < 2; mm++)
#pragma unroll
                for (int nn = 0; nn < 8; nn++)
#pragma unroll
                    for (int r = 0; r < 4; r++) acc[mm][nn][r] = 0.f;
#pragma unroll
            for (int ks = 0; ks < 16; ks++) {
                uint32_t a0[4], a1[4];
                ldsm4t(a0, sb + QK_SS + ((ks * 16 + tr) * SSTR + mbase + tc) * 2);
                ldsm4t(a1, sb + QK_SS + ((ks * 16 + tr) * SSTR + mbase + 16 + tc) * 2);
#pragma unroll
                for (int ng = 0; ng < 4; ng++) {
                    uint32_t bb[4];
                    ldsm4(bb, wb + ((nbase + ng * 16 + lr) * WSTR + ks * 16 + lk) * 2);
                    mma2(acc[0][2 * ng],     a0, bb[0], bb[2]);
                    mma2(acc[0][2 * ng + 1], a0, bb[1], bb[3]);
                    mma2(acc[1][2 * ng],     a1, bb[0], bb[2]);
                    mma2(acc[1][2 * ng + 1], a1, bb[1], bb[3]);
                }
            }
            __nv_bfloat16* op = ((m == 0) ? g_q : g_k) + (size_t)b * Nsp * Cch;
#pragma unroll
            for (int mm = 0; mm < 2; mm++) {
                int i_row = i0 + mbase + mm * 16 + g;
#pragma unroll
                for (int nn = 0; nn < 8; nn++) {
                    int oc = half * 128 + nbase + nn * 8 + 2 * qt;
                    float bia0 = bia[oc], bia1 = bia[oc + 1];
                    __nv_bfloat162 p0 = __floats2bfloat162_rn((acc[mm][nn][0] + bia0) * scale,
                                                              (acc[mm][nn][1] + bia1) * scale);
                    __nv_bfloat162 p1 = __floats2bfloat162_rn((acc[mm][nn][2] + bia0) * scale,
                                                              (acc[mm][nn][3] + bia1) * scale);
                    *(__nv_bfloat162*)(op + (size_t)i_row * Cch + oc) = p0;
                    *(__nv_bfloat162*)(op + (size_t)(i_row + 8) * Cch + oc) = p1;
                }
            }
        } else {
            // ---- v: D[o][i]; warp: 16 o rows x 128 i ----
            const int obase = warp * 16;
            float acc[16][4];
#pragma unroll
            for (int nn = 0; nn < 16; nn++)
#pragma unroll
                for (int r = 0; r < 4; r++) acc[nn][r] = 0.f;
#pragma unroll
            for (int ks = 0; ks < 16; ks++) {
                uint32_t a[4];
                ldsm4(a, wb + ((obase + lr) * WSTR + ks * 16 + lk) * 2);
#pragma unroll
                for (int ng = 0; ng < 8; ng++) {
                    uint32_t bb[4];
                    ldsm4t(bb, sb + QK_SS + ((ks * 16 + tr) * SSTR + ng * 16 + tc) * 2);
                    mma2(acc[2 * ng],     a, bb[0], bb[2]);
                    mma2(acc[2 * ng + 1], a, bb[1], bb[3]);
                }
            }
            __nv_bfloat16* op = g_v + (size_t)b * Cch * Nsp;
            int o_row = half * 128 + obase + g;
            float b0v = bia[o_row];
            float b1v = bia[o_row + 8];
#pragma unroll
            for (int nn = 0; nn < 16; nn++) {
                int col = i0 + nn * 8 + 2 * qt;
                __nv_bfloat162 p0 = __floats2bfloat162_rn(acc[nn][0] + b0v, acc[nn][1] + b0v);
                __nv_bfloat162 p1 = __floats2bfloat162_rn(acc[nn][2] + b1v, acc[nn][3] + b1v);
                *(__nv_bfloat162*)(op + (size_t)o_row * Nsp + col) = p0;
                *(__nv_bfloat162*)(op + (size_t)(o_row + 8) * Nsp + col) = p1;
            }
        }

        if (p < 5) {
            __syncthreads();           // all warps done reading buf (p&1)
            if (p + 2 < 6) {           // prefetch phase p+2 into buf (p&1)
                const int m2 = (p + 2) >> 1, h2 = (p + 2) & 1;
                const __nv_bfloat16* W2 = wsrc0[m2] + (size_t)h2 * 128 * Cch;
#pragma unroll
                for (int kk = 0; kk < 16; kk++) {
                    int idx = tid + kk * 256;
                    int o = idx >> 5, c8 = (idx & 31) * 8;
                    cp16(sb + (p & 1) * WBUF + (o * WSTR + c8) * 2, W2 + (size_t)o * Cch + c8);
                }
                CP_COMMIT;
                CP_WAIT(1);            // phase p+1's W resident
            } else {
                CP_WAIT(0);            // last in-flight group (phase 5's W)
            }
            __syncthreads();
        }
    }
}

// ---------------- Fused flash attention (round-13 core, best known) ----------
#define QSTR 264
#define VSTR 72
#define SQO  0
#define SKO  (128 * QSTR * 2)                 // 67584
#define SKBUF (64 * QSTR * 2)                 // 33792
#define SVO  (SKO + 2 * SKBUF)                // 135168
#define SVBUF (256 * VSTR * 2)                // 36864
#define ATTN_SMEM (SVO + 2 * SVBUF)           // 208896

__global__ __launch_bounds__(256, 1) void attn_kernel() {
    extern __shared__ __align__(128) char smem[];
    const uint32_t sb = smem_u32(smem);
    const int tid = threadIdx.x, lane = tid & 31, warp = tid >> 5;
    const int g = lane >> 2, qt = lane & 3;
    const int R = warp * 16;
    const int b = blockIdx.y, i0 = blockIdx.x * 128;

    const __nv_bfloat16* qg = g_q + ((size_t)b * Nsp + i0) * Cch;
    const __nv_bfloat16* kg = g_k + (size_t)b * Nsp * Cch;
    const __nv_bfloat16* vg = g_v + (size_t)b * Cch * Nsp;

#pragma unroll
    for (int kk = 0; kk < 16; kk++) {
        int idx = tid + kk * 256;
        int row = idx >> 5, c = (idx & 31) * 8;
        cp16(sb + SQO + (row * QSTR + c) * 2, qg + (size_t)row * Cch + c);
    }
#pragma unroll
    for (int kk = 0; kk < 8; kk++) {
        int idx = tid + kk * 256;
        int row = idx >> 5, c = (idx & 31) * 8;
        cp16(sb + SKO + (row * QSTR + c) * 2, kg + (size_t)row * Cch + c);
    }
#pragma unroll
    for (int kk = 0; kk < 8; kk++) {
        int idx = tid + kk * 256;
        int row = idx >> 3, c = (idx & 7) * 8;
        cp16(sb + SVO + (row * VSTR + c) * 2, vg + (size_t)row * Nsp + c);
    }
    CP_COMMIT;
#pragma unroll
    for (int kk = 0; kk < 8; kk++) {
        int idx = tid + kk * 256;
        int row = idx >> 5, c = (idx & 31) * 8;
        cp16(sb + SKO + SKBUF + (row * QSTR + c) * 2, kg + (size_t)(64 + row) * Cch + c);
    }
#pragma unroll
    for (int kk = 0; kk < 8; kk++) {
        int idx = tid + kk * 256;
        int row = idx >> 3, c = (idx & 7) * 8;
        cp16(sb + SVO + SVBUF + (row * VSTR + c) * 2, vg + (size_t)row * Nsp + 64 + c);
    }
    CP_COMMIT;
    CP_WAIT(1);
    __syncthreads();

    const int lr = lane & 15, lk = (lane >> 4) * 8;

    uint32_t qf[16][4];
    {
        const uint32_t qfb = sb + SQO + ((R + lr) * QSTR + lk) * 2;
#pragma unroll
        for (int ks = 0; ks < 16; ks++) ldsm4(qf[ks], qfb + ks * 32);
    }

    float o_acc[32][4];
#pragma unroll
    for (int nt = 0; nt < 32; nt++)
#pragma unroll
        for (int r = 0; r < 4; r++) o_acc[nt][r] = 0.f;
    float l0 = 0.f, l1 = 0.f;
    const float LOG2E = 1.4426950408889634f;

    for (int t = 0; t < 64; t++) {
        const int buf = t & 1;
        const uint32_t kfb = sb + SKO + buf * SKBUF + (lr * QSTR + lk) * 2;
        const uint32_t vfb = sb + SVO + buf * SVBUF + (lr * VSTR + lk) * 2;

#pragma unroll
        for (int jh = 0; jh < 2; jh++) {
            float s_acc[4][4];
#pragma unroll
            for (int nt = 0; nt < 4; nt++)
#pragma unroll
                for (int r = 0; r < 4; r++) s_acc[nt][r] = 0.f;
#pragma unroll
            for (int ks = 0; ks < 16; ks++) {
#pragma unroll
                for (int jg = 0; jg < 2; jg++) {
                    uint32_t bb[4];
                    ldsm4(bb, kfb + (jh * 2 + jg) * (16 * QSTR * 2) + ks * 32);
                    mma2(s_acc[2 * jg],     qf[ks], bb[0], bb[2]);
                    mma2(s_acc[2 * jg + 1], qf[ks], bb[1], bb[3]);
                }
            }

            uint32_t pf[2][4];
#pragma unroll
            for (int kh = 0; kh < 2; kh++) {
#pragma unroll
                for (int hf2 = 0; hf2 < 2; hf2++) {
                    int nt = 2 * kh + hf2;
                    float p0 = ex2(s_acc[nt][0] * LOG2E);
                    float p1 = ex2(s_acc[nt][1] * LOG2E);
                    float p2 = ex2(s_acc[nt][2] * LOG2E);
                    float p3 = ex2(s_acc[nt][3] * LOG2E);
                    l0 += p0 + p1;
                    l1 += p2 + p3;
                    __nv_bfloat162 h0 = __floats2bfloat162_rn(p0, p1);
                    __nv_bfloat162 h1 = __floats2bfloat162_rn(p2, p3);
                    pf[kh][2 * hf2]     = *reinterpret_cast<uint32_t*>(&h0);
                    pf[kh][2 * hf2 + 1] = *reinterpret_cast<uint32_t*>(&h1);
                }
            }

#pragma unroll
            for (int kh = 0; kh < 2; kh++) {
#pragma unroll
                for (int ct = 0; ct < 16; ct++) {
                    uint32_t bb[4];
                    ldsm4(bb, vfb + ct * (16 * VSTR * 2) + (jh * 2 + kh) * 32);
                    mma2(o_acc[2 * ct],     pf[kh], bb[0], bb[2]);
                    mma2(o_acc[2 * ct + 1], pf[kh], bb[1], bb[3]);
                }
            }
        }

        CP_WAIT(0);
        __syncthreads();

        if (t < 62) {
            const int tt = t + 2;
#pragma unroll
            for (int kk = 0; kk < 8; kk++) {
                int idx = tid + kk * 256;
                int row = idx >> 5, c = (idx & 31) * 8;
                cp16(sb + SKO + buf * SKBUF + (row * QSTR + c) * 2,
                     kg + (size_t)(tt * 64 + row) * Cch + c);
            }
#pragma unroll
            for (int kk = 0; kk < 8; kk++) {
                int idx = tid + kk * 256;
                int row = idx >> 3, c = (idx & 7) * 8;
                cp16(sb + SVO + buf * SVBUF + (row * VSTR + c) * 2,
                     vg + (size_t)row * Nsp + tt * 64 + c);
            }
            CP_COMMIT;
        }
    }

    l0 += __shfl_xor_sync(0xffffffffu, l0, 1);
    l0 += __shfl_xor_sync(0xffffffffu, l0, 2);
    l1 += __shfl_xor_sync(0xffffffffu, l1, 1);
    l1 += __shfl_xor_sync(0xffffffffu, l1, 2);
    float inv0 = 1.f / l0, inv1 = 1.f / l1;

    __nv_bfloat16* h0row = g_h + ((size_t)b * Nsp + i0 + R + g) * Cch;
    __nv_bfloat16* h1row = g_h + ((size_t)b * Nsp + i0 + R + g + 8) * Cch;
#pragma unroll
    for (int nt = 0; nt < 32; nt++) {
        int col = nt * 8 + 2 * qt;
        __nv_bfloat162 a0 = __floats2bfloat162_rn(o_acc[nt][0] * inv0, o_acc[nt][1] * inv0);
        __nv_bfloat162 a1 = __floats2bfloat162_rn(o_acc[nt][2] * inv1, o_acc[nt][3] * inv1);
        *(uint32_t*)(h0row + col) = *reinterpret_cast<uint32_t*>(&a0);
        *(uint32_t*)(h1row + col) = *reinterpret_cast<uint32_t*>(&a1);
    }
}

// ---------------- Proj (single-pass) + residual (fp32 out) -------------------
#define PWS 0
#define PHS (128 * WSTR * 2)                   // 67584
#define PROJ_SMEM (PHS + 128 * WSTR * 2)       // 135168

__global__ __launch_bounds__(256, 1) void proj_kernel(const float* __restrict__ bp,
                                                      const float* __restrict__ xin,
                                                      float* __restrict__ out) {
    extern __shared__ __align__(128) char smem[];
    const uint32_t sb = smem_u32(smem);
    const int b = blockIdx.z;
    const int i0 = blockIdx.x * 128;
    const int o0 = blockIdx.y * 128;

    const int tid = threadIdx.x, lane = tid & 31, warp = tid >> 5;
    const int g = lane >> 2, qt = lane & 3;
    const int lr = lane & 15, lk = (lane >> 4) * 8;
    const int wm = warp & 3, wn = warp >> 2;

#pragma unroll
    for (int kk = 0; kk < 16; kk++) {
        int idx = tid + kk * 256;
        int o = idx >> 5, c8 = (idx & 31) * 8;
        cp16(sb + PWS + (o * WSTR + c8) * 2, g_wp + (size_t)(o0 + o) * Cch + c8);
    }
#pragma unroll
    for (int kk = 0; kk < 16; kk++) {
        int idx = tid + kk * 256;
        int i = idx >> 5, c8 = (idx & 31) * 8;
        cp16(sb + PHS + (i * WSTR + c8) * 2, g_h + ((size_t)b * Nsp + i0 + i) * Cch + c8);
    }
    CP_COMMIT;
    CP_WAIT(0);
    __syncthreads();

    float acc[2][8][4];
#pragma unroll
    for (int mm = 0; mm < 2; mm++)
#pragma unroll
        for (int nn = 0; nn < 8; nn++)
#pragma unroll
            for (int r = 0; r < 4; r++) acc[mm][nn][r] = 0.f;

#pragma unroll
    for (int ks = 0; ks < 16; ks++) {
        uint32_t a0[4], a1[4];
        ldsm4(a0, sb + PWS + ((wm * 32 + lr) * WSTR + ks * 16 + lk) * 2);
        ldsm4(a1, sb + PWS + ((wm * 32 + 16 + lr) * WSTR + ks * 16 + lk) * 2);
#pragma unroll
        for (int ng = 0; ng < 4; ng++) {
            uint32_t bb[4];
            ldsm4(bb, sb + PHS + ((wn * 64 + ng * 16 + lr) * WSTR + ks * 16 + lk) * 2);
            mma2(acc[0][2 * ng],     a0, bb[0], bb[2]);
            mma2(acc[0][2 * ng + 1], a0, bb[1], bb[3]);
            mma2(acc[1][2 * ng],     a1, bb[0], bb[2]);
            mma2(acc[1][2 * ng + 1], a1, bb[1], bb[3]);
        }
    }

    const float* xp = xin + (size_t)b * Cch * Nsp;
    float* op = out + (size_t)b * Cch * Nsp;
#pragma unroll
    for (int mm = 0; mm < 2; mm++) {
        int o_row = o0 + wm * 32 + mm * 16 + g;
        float b0v = bp[o_row];
        float b1v = bp[o_row + 8];
#pragma unroll
        for (int nn = 0; nn < 8; nn++) {
            int col = i0 + wn * 64 + nn * 8 + 2 * qt;
            size_t idx0 = (size_t)o_row * Nsp + col;
            size_t idx1 = (size_t)(o_row + 8) * Nsp + col;
            float2 x0 = *(const float2*)(xp + idx0);
            float2 x1 = *(const float2*)(xp + idx1);
            float2 r0 = make_float2(acc[mm][nn][0] + b0v + x0.x, acc[mm][nn][1] + b0v + x0.y);
            float2 r1 = make_float2(acc[mm][nn][2] + b1v + x1.x, acc[mm][nn][3] + b1v + x1.y);
            *(float2*)(op + idx0) = r0;
            *(float2*)(op + idx1) = r1;
        }
    }
}

// ---------------- launch -----------------------------------------------------
extern "C" void kernel_launch(void* const* d_in, const int* in_sizes, int n_in,
                              void* d_out, int out_size) {
    (void)in_sizes; (void)n_in; (void)out_size;
    const float* x     = (const float*)d_in[0];
    const float* gamma = (const float*)d_in[1];
    const float* beta  = (const float*)d_in[2];
    const float* wq    = (const float*)d_in[3];
    const float* bq    = (const float*)d_in[4];
    const float* wk    = (const float*)d_in[5];
    const float* bk    = (const float*)d_in[6];
    const float* wv    = (const float*)d_in[7];
    const float* bv    = (const float*)d_in[8];
    const float* wp    = (const float*)d_in[9];
    const float* bp    = (const float*)d_in[10];
    float* out = (float*)d_out;

    wcvt_kernel<<<dim3(64, 4), 256>>>(wq, wk, wv, wp);
    gn_kernel<<<Bsz * Gg, 256>>>(x, gamma, beta);
    cudaFuncSetAttribute(qkv_kernel, cudaFuncAttributeMaxDynamicSharedMemorySize, QKV_SMEM);
    qkv_kernel<<<dim3(Nsp / 128, Bsz), 256, QKV_SMEM>>>(bq, bk, bv);
    cudaFuncSetAttribute(attn_kernel, cudaFuncAttributeMaxDynamicSharedMemorySize, ATTN_SMEM);
    attn_kernel<<<dim3(Nsp / 128, Bsz), 256, ATTN_SMEM>>>();
    cudaFuncSetAttribute(proj_kernel, cudaFuncAttributeMaxDynamicSharedMemorySize, PROJ_SMEM);
    proj_kernel<<<dim3(Nsp / 128, Cch / 128, Bsz), 256, PROJ_SMEM>>>(bp, x, out);
}